// round 1
// baseline (speedup 1.0000x reference)
#include <cuda_runtime.h>
#include <math.h>

#define NN 16384
#define EPSV 1e-5f

// ---------- sizes ----------
#define Y1SZ (NN*8*22*22)     // 63,438,848
#define P1SZ (NN*8*11*11)     // 15,859,712
#define Y2SZ (NN*10*7*7)      //  8,028,160
#define P2SZ (NN*10*9)        //  1,474,560
#define THSZ (NN*6)

// stats layout: [0..7]=s1 [8..15]=q1 [16..25]=s2 [26..35]=q2 [36..163]=s3 [164..291]=q3
#define NSTATS 292

__device__ float g_y1[Y1SZ];
__device__ float g_p1[P1SZ];
__device__ float g_y2[Y2SZ];
__device__ float g_p2[P2SZ];
__device__ float g_theta[THSZ];
__device__ float g_stats[NSTATS];

// ---------------- K0: zero stats ----------------
__global__ void k0_zero() {
    int t = threadIdx.x;
    if (t < NSTATS) g_stats[t] = 0.0f;
}

// ---------------- K1: conv1 7x7 (1->8) + BN1 stats ----------------
// block = 176 threads = 8 channels x 22 output rows, one sample per block
__global__ __launch_bounds__(176) void k1_conv1(const float* __restrict__ x,
                                                const float* __restrict__ w1) {
    __shared__ float sx[784];
    __shared__ float sw[392];
    __shared__ float ssum[8], ssq[8];
    const int n = blockIdx.x;
    const int t = threadIdx.x;
    const float* xin = x + n * 784;
    for (int i = t; i < 784; i += 176) sx[i] = xin[i];
    for (int i = t; i < 392; i += 176) sw[i] = w1[i];
    if (t < 8) { ssum[t] = 0.0f; ssq[t] = 0.0f; }
    __syncthreads();

    const int c = t / 22;
    const int oh = t % 22;
    float acc[22];
#pragma unroll
    for (int i = 0; i < 22; i++) acc[i] = 0.0f;
    const float* wc = &sw[c * 49];

    for (int kh = 0; kh < 7; kh++) {
        float xr[28];
        const float* row = &sx[(oh + kh) * 28];
#pragma unroll
        for (int i = 0; i < 28; i++) xr[i] = row[i];
#pragma unroll
        for (int kw = 0; kw < 7; kw++) {
            const float wv = wc[kh * 7 + kw];
#pragma unroll
            for (int ow = 0; ow < 22; ow++) acc[ow] += wv * xr[ow + kw];
        }
    }

    float s = 0.0f, q = 0.0f;
    float* outp = g_y1 + ((size_t)(n * 8 + c) * 22 + oh) * 22;
#pragma unroll
    for (int i = 0; i < 22; i++) {
        outp[i] = acc[i];
        s += acc[i];
        q += acc[i] * acc[i];
    }
    atomicAdd(&ssum[c], s);
    atomicAdd(&ssq[c], q);
    __syncthreads();
    if (t < 8) {
        atomicAdd(&g_stats[t], ssum[t]);
        atomicAdd(&g_stats[8 + t], ssq[t]);
    }
}

// ---------------- K2: BN1 + maxpool2 + relu ----------------
__global__ void k2_bnpool1(const float* __restrict__ g1, const float* __restrict__ b1) {
    int idx = blockIdx.x * blockDim.x + threadIdx.x;
    if (idx >= P1SZ) return;
    int pw = idx % 11;
    int tt = idx / 11;
    int ph = tt % 11; tt /= 11;
    int c = tt % 8;
    int n = tt / 8;
    const float cnt = 7929856.0f; // N*22*22
    float m = g_stats[c] / cnt;
    float v = g_stats[8 + c] / cnt - m * m;
    float sc = g1[c] * rsqrtf(v + EPSV);
    float sh = b1[c] - m * sc;
    const float* base = g_y1 + ((size_t)(n * 8 + c) * 22 + 2 * ph) * 22 + 2 * pw;
    float a = base[0] * sc + sh;
    float b = base[1] * sc + sh;
    float c2 = base[22] * sc + sh;
    float d = base[23] * sc + sh;
    float mx = fmaxf(fmaxf(a, b), fmaxf(c2, d));
    g_p1[idx] = fmaxf(mx, 0.0f);
}

// ---------------- K3: conv2 5x5 (8->10) + BN2 stats ----------------
// block = 576 threads, 8 samples per block; 560 active compute threads:
// t -> (local_n, oc, oh); each thread computes one 7-wide output row.
__global__ __launch_bounds__(576) void k3_conv2(const float* __restrict__ w2) {
    __shared__ float sp[8 * 968];
    __shared__ float sw[2000];
    __shared__ float ssum[10], ssq[10];
    const int nb = blockIdx.x * 8;
    const int t = threadIdx.x;
    const float* src = g_p1 + (size_t)nb * 968;
    for (int i = t; i < 8 * 968; i += 576) sp[i] = src[i];
    for (int i = t; i < 2000; i += 576) sw[i] = w2[i];
    if (t < 10) { ssum[t] = 0.0f; ssq[t] = 0.0f; }
    __syncthreads();

    if (t < 560) {
        const int ln = t / 70;
        const int r = t % 70;
        const int oc = r / 7;
        const int oh = r % 7;
        float acc[7];
#pragma unroll
        for (int i = 0; i < 7; i++) acc[i] = 0.0f;
        const float* pin = &sp[ln * 968];

        for (int ic = 0; ic < 8; ic++) {
#pragma unroll
            for (int kh = 0; kh < 5; kh++) {
                float xr[11];
                const float* row = &pin[ic * 121 + (oh + kh) * 11];
#pragma unroll
                for (int i = 0; i < 11; i++) xr[i] = row[i];
                const float* wr = &sw[((oc * 8 + ic) * 5 + kh) * 5];
#pragma unroll
                for (int kw = 0; kw < 5; kw++) {
                    const float wv = wr[kw];
#pragma unroll
                    for (int ow = 0; ow < 7; ow++) acc[ow] += wv * xr[ow + kw];
                }
            }
        }

        const int n = nb + ln;
        float s = 0.0f, q = 0.0f;
        float* o = g_y2 + ((size_t)(n * 10 + oc) * 7 + oh) * 7;
#pragma unroll
        for (int i = 0; i < 7; i++) {
            o[i] = acc[i];
            s += acc[i];
            q += acc[i] * acc[i];
        }
        atomicAdd(&ssum[oc], s);
        atomicAdd(&ssq[oc], q);
    }
    __syncthreads();
    if (t < 10) {
        atomicAdd(&g_stats[16 + t], ssum[t]);
        atomicAdd(&g_stats[26 + t], ssq[t]);
    }
}

// ---------------- K4: BN2 + maxpool2 + relu ----------------
__global__ void k4_bnpool2(const float* __restrict__ g2, const float* __restrict__ b2) {
    int idx = blockIdx.x * blockDim.x + threadIdx.x;
    if (idx >= P2SZ) return;
    int pw = idx % 3;
    int tt = idx / 3;
    int ph = tt % 3; tt /= 3;
    int c = tt % 10;
    int n = tt / 10;
    const float cnt = 802816.0f; // N*7*7
    float m = g_stats[16 + c] / cnt;
    float v = g_stats[26 + c] / cnt - m * m;
    float sc = g2[c] * rsqrtf(v + EPSV);
    float sh = b2[c] - m * sc;
    const float* base = g_y2 + ((size_t)(n * 10 + c) * 7 + 2 * ph) * 7 + 2 * pw;
    float a = base[0] * sc + sh;
    float b = base[1] * sc + sh;
    float c2 = base[7] * sc + sh;
    float d = base[8] * sc + sh;
    float mx = fmaxf(fmaxf(a, b), fmaxf(c2, d));
    g_p2[idx] = fmaxf(mx, 0.0f);
}

// ---------------- K5: conv3 (1x1, 10->128) stats only ----------------
// block = 128 threads (one per out channel), 8 samples per block
__global__ __launch_bounds__(128) void k5_conv3stats(const float* __restrict__ w3) {
    __shared__ float sp[8 * 90];
    const int nb = blockIdx.x * 8;
    const int t = threadIdx.x;
    const float* src = g_p2 + (size_t)nb * 90;
    for (int i = t; i < 8 * 90; i += 128) sp[i] = src[i];
    __syncthreads();

    float w[10];
#pragma unroll
    for (int k = 0; k < 10; k++) w[k] = w3[t * 10 + k];

    float s = 0.0f, q = 0.0f;
    for (int ln = 0; ln < 8; ln++) {
        const float* pv = &sp[ln * 90];
#pragma unroll
        for (int p = 0; p < 9; p++) {
            float y = 0.0f;
#pragma unroll
            for (int k = 0; k < 10; k++) y += w[k] * pv[k * 9 + p];
            s += y;
            q += y * y;
        }
    }
    atomicAdd(&g_stats[36 + t], s);
    atomicAdd(&g_stats[164 + t], q);
}

// ---------------- K6: conv3 + BN3 + relu + avgpool + FC -> theta ----------------
// block = 128 threads (one per hidden channel), one sample per block
__global__ __launch_bounds__(128) void k6_theta(const float* __restrict__ w3,
                                                const float* __restrict__ g3,
                                                const float* __restrict__ b3,
                                                const float* __restrict__ fw,
                                                const float* __restrict__ fb) {
    __shared__ float sp[90];
    __shared__ float wsum[4][6];
    const int n = blockIdx.x;
    const int t = threadIdx.x;
    if (t < 90) sp[t] = g_p2[(size_t)n * 90 + t];
    __syncthreads();

    const int c = t;
    const float cnt = 147456.0f; // N*9
    float m = g_stats[36 + c] / cnt;
    float v = g_stats[164 + c] / cnt - m * m;
    float sc = g3[c] * rsqrtf(v + EPSV);
    float sh = b3[c] - m * sc;

    float w[10];
#pragma unroll
    for (int k = 0; k < 10; k++) w[k] = w3[c * 10 + k];

    float h = 0.0f;
#pragma unroll
    for (int p = 0; p < 9; p++) {
        float y = 0.0f;
#pragma unroll
        for (int k = 0; k < 10; k++) y += w[k] * sp[k * 9 + p];
        y = y * sc + sh;
        h += fmaxf(y, 0.0f);
    }
    h *= (1.0f / 9.0f);

    float pj[6];
#pragma unroll
    for (int j = 0; j < 6; j++) pj[j] = fw[j * 128 + c] * h;
#pragma unroll
    for (int off = 16; off >= 1; off >>= 1) {
#pragma unroll
        for (int j = 0; j < 6; j++)
            pj[j] += __shfl_xor_sync(0xffffffffu, pj[j], off);
    }
    const int lane = t & 31, warp = t >> 5;
    if (lane == 0) {
#pragma unroll
        for (int j = 0; j < 6; j++) wsum[warp][j] = pj[j];
    }
    __syncthreads();
    if (t < 6) {
        g_theta[(size_t)n * 6 + t] =
            wsum[0][t] + wsum[1][t] + wsum[2][t] + wsum[3][t] + fb[t];
    }
}

// ---------------- K7: affine grid + bilinear sampler ----------------
__global__ void k7_sample(const float* __restrict__ x, float* __restrict__ out) {
    int idx = blockIdx.x * blockDim.x + threadIdx.x;
    if (idx >= NN * 784) return;
    const int n = idx / 784;
    const int p = idx % 784;
    const int py = p / 28;
    const int px = p % 28;

    const float step = 2.0f / 27.0f;
    const float xn = -1.0f + step * px;
    const float yn = -1.0f + step * py;

    const float* th = g_theta + (size_t)n * 6;
    const float gx = th[0] * xn + th[1] * yn + th[2];
    const float gy = th[3] * xn + th[4] * yn + th[5];

    const float ix = (gx + 1.0f) * 13.5f; // 0.5*(W-1)
    const float iy = (gy + 1.0f) * 13.5f;

    const float x0f = floorf(ix);
    const float y0f = floorf(iy);
    const float wx = ix - x0f;
    const float wy = iy - y0f;

    int x0 = (int)x0f; x0 = min(max(x0, 0), 27);
    int x1 = min(x0 + 1, 27);
    int y0 = (int)y0f; y0 = min(max(y0, 0), 27);
    int y1 = min(y0 + 1, 27);

    const float* img = x + (size_t)n * 784;
    const float v00 = img[y0 * 28 + x0];
    const float v01 = img[y0 * 28 + x1];
    const float v10 = img[y1 * 28 + x0];
    const float v11 = img[y1 * 28 + x1];

    const float top = v00 * (1.0f - wx) + v01 * wx;
    const float bot = v10 * (1.0f - wx) + v11 * wx;
    out[idx] = top * (1.0f - wy) + bot * wy;
}

// ---------------- launcher ----------------
extern "C" void kernel_launch(void* const* d_in, const int* in_sizes, int n_in,
                              void* d_out, int out_size) {
    const float* x  = (const float*)d_in[0];
    const float* w1 = (const float*)d_in[1];
    const float* g1 = (const float*)d_in[2];
    const float* b1 = (const float*)d_in[3];
    const float* w2 = (const float*)d_in[4];
    const float* g2 = (const float*)d_in[5];
    const float* b2 = (const float*)d_in[6];
    const float* w3 = (const float*)d_in[7];
    const float* g3 = (const float*)d_in[8];
    const float* b3 = (const float*)d_in[9];
    const float* fw = (const float*)d_in[10];
    const float* fb = (const float*)d_in[11];
    float* out = (float*)d_out;

    k0_zero<<<1, 512>>>();
    k1_conv1<<<NN, 176>>>(x, w1);
    k2_bnpool1<<<(P1SZ + 255) / 256, 256>>>(g1, b1);
    k3_conv2<<<NN / 8, 576>>>(w2);
    k4_bnpool2<<<(P2SZ + 255) / 256, 256>>>(g2, b2);
    k5_conv3stats<<<NN / 8, 128>>>(w3);
    k6_theta<<<NN, 128>>>(w3, g3, b3, fw, fb);
    k7_sample<<<(NN * 784 + 255) / 256, 256>>>(x, out);
}

// round 2
// speedup vs baseline: 1.1212x; 1.1212x over previous
#include <cuda_runtime.h>
#include <math.h>

#define NN 16384
#define EPSV 1e-5f

typedef unsigned long long u64;

// ---------- intermediate buffers ----------
#define M1SZ (NN*8*121)   // pooled max/min of conv1 output (pre-BN)
#define M2SZ (NN*90)      // pooled max/min of conv2 output (pre-BN)
#define THSZ (NN*6)
#define NSTATS 292
// stats layout: [0..7]=s1 [8..15]=q1 [16..25]=s2 [26..35]=q2 [36..163]=s3 [164..291]=q3

__device__ float g_m1[M1SZ];
__device__ float g_n1[M1SZ];
__device__ float g_m2[M2SZ];
__device__ float g_n2[M2SZ];
__device__ float g_theta[THSZ];
__device__ float g_stats[NSTATS];

// ---------- packed f32x2 helpers ----------
__device__ __forceinline__ u64 pk2(float a, float b) {
    u64 r; asm("mov.b64 %0,{%1,%2};" : "=l"(r) : "f"(a), "f"(b)); return r;
}
__device__ __forceinline__ u64 splat2(float a) { return pk2(a, a); }
__device__ __forceinline__ void upk2(u64 v, float& a, float& b) {
    asm("mov.b64 {%0,%1},%2;" : "=f"(a), "=f"(b) : "l"(v));
}
__device__ __forceinline__ u64 fma2(u64 a, u64 b, u64 c) {
    u64 d; asm("fma.rn.f32x2 %0,%1,%2,%3;" : "=l"(d) : "l"(a), "l"(b), "l"(c)); return d;
}

// ---------------- K0: zero stats ----------------
__global__ void k0_zero() {
    int t = threadIdx.x;
    if (t < NSTATS) g_stats[t] = 0.0f;
}

// ---------------- K1: conv1 7x7 (1->8) + BN1 stats + pooled max/min ----------------
// thread = (sample, channel, row-pair ph). Computes output rows 2ph, 2ph+1 (22 wide)
// with packed f32x2 FMA, accumulates BN stats, writes 2x2-pooled max & min.
template<bool D0, bool D1>
__device__ __forceinline__ void k1_row(const float* __restrict__ row,
                                       const float* __restrict__ wc,
                                       int kh0, int kh1, u64* acc0, u64* acc1) {
    float x[28];
#pragma unroll
    for (int i = 0; i < 7; i++) {
        float4 v = *reinterpret_cast<const float4*>(row + 4 * i);
        x[4*i] = v.x; x[4*i+1] = v.y; x[4*i+2] = v.z; x[4*i+3] = v.w;
    }
    u64 e[14], o[13];
#pragma unroll
    for (int j = 0; j < 14; j++) e[j] = pk2(x[2*j], x[2*j+1]);
#pragma unroll
    for (int j = 0; j < 13; j++) o[j] = pk2(x[2*j+1], x[2*j+2]);
#pragma unroll
    for (int kw = 0; kw < 7; kw++) {
        const u64* p = (kw & 1) ? (o + (kw >> 1)) : (e + (kw >> 1));
        if (D0) {
            u64 w = splat2(wc[kh0*7 + kw]);
#pragma unroll
            for (int j = 0; j < 11; j++) acc0[j] = fma2(p[j], w, acc0[j]);
        }
        if (D1) {
            u64 w = splat2(wc[kh1*7 + kw]);
#pragma unroll
            for (int j = 0; j < 11; j++) acc1[j] = fma2(p[j], w, acc1[j]);
        }
    }
}

__global__ __launch_bounds__(176) void k1_conv1(const float* __restrict__ x,
                                                const float* __restrict__ w1) {
    __shared__ __align__(16) float sx[1568];
    __shared__ float sw[392];
    __shared__ float ssum[8], ssq[8];
    const int nb = blockIdx.x * 2;
    const int t = threadIdx.x;
    const float* xin = x + (size_t)nb * 784;
    for (int i = t; i < 1568; i += 176) sx[i] = xin[i];
    for (int i = t; i < 392; i += 176) sw[i] = w1[i];
    if (t < 8) { ssum[t] = 0.0f; ssq[t] = 0.0f; }
    __syncthreads();

    const int ln = t / 88;
    const int r  = t % 88;
    const int c  = r / 11;
    const int ph = r % 11;
    const float* xt = sx + ln * 784 + 2 * ph * 28;
    const float* wc = sw + c * 49;

    u64 acc0[11], acc1[11];
#pragma unroll
    for (int j = 0; j < 11; j++) { acc0[j] = 0ull; acc1[j] = 0ull; }

    k1_row<true, false>(xt, wc, 0, 0, acc0, acc1);
#pragma unroll 1
    for (int rr = 1; rr < 7; rr++)
        k1_row<true, true>(xt + rr * 28, wc, rr, rr - 1, acc0, acc1);
    k1_row<false, true>(xt + 7 * 28, wc, 0, 6, acc0, acc1);

    float s = 0.0f, q = 0.0f;
    const int n = nb + ln;
    float* om = g_m1 + (((size_t)n * 8 + c) * 11 + ph) * 11;
    float* on = g_n1 + (((size_t)n * 8 + c) * 11 + ph) * 11;
#pragma unroll
    for (int j = 0; j < 11; j++) {
        float a, b, d, e2;
        upk2(acc0[j], a, b);
        upk2(acc1[j], d, e2);
        s += (a + b) + (d + e2);
        q += a * a + b * b + d * d + e2 * e2;
        om[j] = fmaxf(fmaxf(a, b), fmaxf(d, e2));
        on[j] = fminf(fminf(a, b), fminf(d, e2));
    }
    atomicAdd(&ssum[c], s);
    atomicAdd(&ssq[c], q);
    __syncthreads();
    if (t < 8) {
        atomicAdd(&g_stats[t], ssum[t]);
        atomicAdd(&g_stats[8 + t], ssq[t]);
    }
}

// ---------------- K3: fused BN1+pool-select+relu stage, conv2 5x5 (8->10),
//                  BN2 stats, pooled max/min output ----------------
__device__ __forceinline__ void k3_row(const float* __restrict__ row,
                                       const float* __restrict__ wb,
                                       u64 acc[5][4]) {
    float x[12];
#pragma unroll
    for (int i = 0; i < 3; i++) {
        float4 v = *reinterpret_cast<const float4*>(row + 4 * i);
        x[4*i] = v.x; x[4*i+1] = v.y; x[4*i+2] = v.z; x[4*i+3] = v.w;
    }
    u64 e[6], o[5];
#pragma unroll
    for (int j = 0; j < 6; j++) e[j] = pk2(x[2*j], x[2*j+1]);
#pragma unroll
    for (int j = 0; j < 5; j++) o[j] = pk2(x[2*j+1], x[2*j+2]);
#pragma unroll
    for (int kw = 0; kw < 5; kw++) {
        const u64* p = (kw & 1) ? (o + (kw >> 1)) : (e + (kw >> 1));
#pragma unroll
        for (int u = 0; u < 5; u++) {
            u64 w = splat2(wb[u * 200 + kw]);  // oc stride in w2 = 8*5*5
#pragma unroll
            for (int j = 0; j < 4; j++) acc[u][j] = fma2(p[j], w, acc[u][j]);
        }
    }
}

__global__ __launch_bounds__(128) void k3_conv2(const float* __restrict__ w2,
                                                const float* __restrict__ g1,
                                                const float* __restrict__ b1) {
    __shared__ __align__(16) float sp[8448];  // staged p1 [8 samples][8 ic][11][12]; later aliased as y2 buf
    __shared__ float swv[2000];
    __shared__ float sc1s[8], sh1s[8];
    __shared__ float ssum[10], ssq[10];
    const int nb = blockIdx.x * 8;
    const int t = threadIdx.x;

    if (t < 8) {
        const float cnt = 7929856.0f;  // N*22*22
        float m = g_stats[t] / cnt;
        float v = g_stats[8 + t] / cnt - m * m;
        float sc = g1[t] * rsqrtf(v + EPSV);
        sc1s[t] = sc;
        sh1s[t] = b1[t] - m * sc;
    }
    if (t < 10) { ssum[t] = 0.0f; ssq[t] = 0.0f; }
    for (int i = t; i < 2000; i += 128) swv[i] = w2[i];
    __syncthreads();

    // stage p1 = relu(BN1-select(max/min)) into padded smem tile
    {
        const float* mbase = g_m1 + (size_t)nb * 968;
        const float* nbase = g_n1 + (size_t)nb * 968;
        for (int i = t; i < 7744; i += 128) {
            int rem = i % 968;
            int c = rem / 121;
            int p = rem % 121;
            int s = i / 968;
            float sc = sc1s[c], sh = sh1s[c];
            float mx = mbase[i], mn = nbase[i];
            float v = sc * (sc >= 0.0f ? mx : mn) + sh;
            sp[((s * 8 + c) * 11 + p / 11) * 12 + (p % 11)] = fmaxf(v, 0.0f);
        }
        for (int i = t; i < 704; i += 128) sp[i * 12 + 11] = 0.0f;  // pad col
    }
    __syncthreads();

    u64 acc[5][4];
    int ln = 0, oc0 = 0, oh = 0;
    if (t < 112) {
        ln = t / 14;
        int r = t % 14;
        oc0 = (r / 7) * 5;
        oh = r % 7;
#pragma unroll
        for (int u = 0; u < 5; u++)
#pragma unroll
            for (int j = 0; j < 4; j++) acc[u][j] = 0ull;

        const float* pin = sp + ln * 1056;
        for (int ic = 0; ic < 8; ic++) {
#pragma unroll 1
            for (int kh = 0; kh < 5; kh++) {
                k3_row(pin + ic * 132 + (oh + kh) * 12,
                       swv + ((oc0 * 8 + ic) * 5 + kh) * 5, acc);
            }
        }
        // BN2 stats over the 7 valid columns
#pragma unroll
        for (int u = 0; u < 5; u++) {
            float a0,a1,a2,a3,a4,a5,a6,a7;
            upk2(acc[u][0], a0, a1);
            upk2(acc[u][1], a2, a3);
            upk2(acc[u][2], a4, a5);
            upk2(acc[u][3], a6, a7);
            float s = a0+a1+a2+a3+a4+a5+a6;
            float q = a0*a0+a1*a1+a2*a2+a3*a3+a4*a4+a5*a5+a6*a6;
            atomicAdd(&ssum[oc0 + u], s);
            atomicAdd(&ssq[oc0 + u], q);
        }
    }
    __syncthreads();        // everyone done reading sp -> safe to alias
    float* ybuf = sp;       // [8][10][7][7]
    if (t < 112) {
#pragma unroll
        for (int u = 0; u < 5; u++) {
            float a[8];
            upk2(acc[u][0], a[0], a[1]);
            upk2(acc[u][1], a[2], a[3]);
            upk2(acc[u][2], a[4], a[5]);
            upk2(acc[u][3], a[6], a[7]);
            float* row = ybuf + ((ln * 10 + oc0 + u) * 7 + oh) * 7;
#pragma unroll
            for (int j = 0; j < 7; j++) row[j] = a[j];
        }
    }
    __syncthreads();
    // pooled max/min (2x2, drops row/col 6 as in VALID pooling)
    for (int i = t; i < 720; i += 128) {
        int ln2 = i / 90;
        int rem = i % 90;
        int oc = rem / 9;
        int p = rem % 9;
        int ph = p / 3, pw = p % 3;
        const float* bb = ybuf + ((ln2 * 10 + oc) * 7 + 2 * ph) * 7 + 2 * pw;
        float a = bb[0], b = bb[1], c = bb[7], d = bb[8];
        size_t oidx = ((size_t)(nb + ln2) * 10 + oc) * 9 + p;
        g_m2[oidx] = fmaxf(fmaxf(a, b), fmaxf(c, d));
        g_n2[oidx] = fminf(fminf(a, b), fminf(c, d));
    }
    if (t < 10) {
        atomicAdd(&g_stats[16 + t], ssum[t]);
        atomicAdd(&g_stats[26 + t], ssq[t]);
    }
}

// ---------------- K5: conv3 (1x1, 10->128) stats (stages p2 from m2/n2) ----------------
__global__ __launch_bounds__(128) void k5_conv3stats(const float* __restrict__ w3,
                                                     const float* __restrict__ g2,
                                                     const float* __restrict__ b2) {
    __shared__ float sp[720];
    __shared__ float sc2s[10], sh2s[10];
    const int nb = blockIdx.x * 8;
    const int t = threadIdx.x;
    if (t < 10) {
        const float cnt = 802816.0f;  // N*7*7
        float m = g_stats[16 + t] / cnt;
        float v = g_stats[26 + t] / cnt - m * m;
        float sc = g2[t] * rsqrtf(v + EPSV);
        sc2s[t] = sc;
        sh2s[t] = b2[t] - m * sc;
    }
    __syncthreads();
    const float* mb = g_m2 + (size_t)nb * 90;
    const float* nb2 = g_n2 + (size_t)nb * 90;
    for (int i = t; i < 720; i += 128) {
        int c = (i % 90) / 9;
        float sc = sc2s[c];
        float v = sc * (sc >= 0.0f ? mb[i] : nb2[i]) + sh2s[c];
        sp[i] = fmaxf(v, 0.0f);
    }
    __syncthreads();

    float w[10];
#pragma unroll
    for (int k = 0; k < 10; k++) w[k] = w3[t * 10 + k];

    float s = 0.0f, q = 0.0f;
    for (int ln = 0; ln < 8; ln++) {
        const float* pv = &sp[ln * 90];
#pragma unroll
        for (int p = 0; p < 9; p++) {
            float y = 0.0f;
#pragma unroll
            for (int k = 0; k < 10; k++) y += w[k] * pv[k * 9 + p];
            s += y;
            q += y * y;
        }
    }
    atomicAdd(&g_stats[36 + t], s);
    atomicAdd(&g_stats[164 + t], q);
}

// ---------------- K6: conv3 + BN3 + relu + avgpool + FC -> theta ----------------
__global__ __launch_bounds__(128) void k6_theta(const float* __restrict__ w3,
                                                const float* __restrict__ g2,
                                                const float* __restrict__ b2,
                                                const float* __restrict__ g3,
                                                const float* __restrict__ b3,
                                                const float* __restrict__ fw,
                                                const float* __restrict__ fb) {
    __shared__ float sp[90];
    __shared__ float sc2s[10], sh2s[10];
    __shared__ float wsum[4][6];
    const int n = blockIdx.x;
    const int t = threadIdx.x;
    if (t < 10) {
        const float cnt = 802816.0f;
        float m = g_stats[16 + t] / cnt;
        float v = g_stats[26 + t] / cnt - m * m;
        float sc = g2[t] * rsqrtf(v + EPSV);
        sc2s[t] = sc;
        sh2s[t] = b2[t] - m * sc;
    }
    __syncthreads();
    if (t < 90) {
        int c = t / 9;
        float sc = sc2s[c];
        float mx = g_m2[(size_t)n * 90 + t];
        float mn = g_n2[(size_t)n * 90 + t];
        float v = sc * (sc >= 0.0f ? mx : mn) + sh2s[c];
        sp[t] = fmaxf(v, 0.0f);
    }
    __syncthreads();

    const int c = t;
    const float cnt3 = 147456.0f;  // N*9
    float m = g_stats[36 + c] / cnt3;
    float v = g_stats[164 + c] / cnt3 - m * m;
    float sc = g3[c] * rsqrtf(v + EPSV);
    float sh = b3[c] - m * sc;

    float w[10];
#pragma unroll
    for (int k = 0; k < 10; k++) w[k] = w3[c * 10 + k];

    float h = 0.0f;
#pragma unroll
    for (int p = 0; p < 9; p++) {
        float y = 0.0f;
#pragma unroll
        for (int k = 0; k < 10; k++) y += w[k] * sp[k * 9 + p];
        y = y * sc + sh;
        h += fmaxf(y, 0.0f);
    }
    h *= (1.0f / 9.0f);

    float pj[6];
#pragma unroll
    for (int j = 0; j < 6; j++) pj[j] = fw[j * 128 + c] * h;
#pragma unroll
    for (int off = 16; off >= 1; off >>= 1) {
#pragma unroll
        for (int j = 0; j < 6; j++)
            pj[j] += __shfl_xor_sync(0xffffffffu, pj[j], off);
    }
    const int lane = t & 31, warp = t >> 5;
    if (lane == 0) {
#pragma unroll
        for (int j = 0; j < 6; j++) wsum[warp][j] = pj[j];
    }
    __syncthreads();
    if (t < 6) {
        g_theta[(size_t)n * 6 + t] =
            wsum[0][t] + wsum[1][t] + wsum[2][t] + wsum[3][t] + fb[t];
    }
}

// ---------------- K7: affine grid + bilinear sampler ----------------
__global__ void k7_sample(const float* __restrict__ x, float* __restrict__ out) {
    int idx = blockIdx.x * blockDim.x + threadIdx.x;
    if (idx >= NN * 784) return;
    const int n = idx / 784;
    const int p = idx % 784;
    const int py = p / 28;
    const int px = p % 28;

    const float step = 2.0f / 27.0f;
    const float xn = -1.0f + step * px;
    const float yn = -1.0f + step * py;

    const float* th = g_theta + (size_t)n * 6;
    const float gx = th[0] * xn + th[1] * yn + th[2];
    const float gy = th[3] * xn + th[4] * yn + th[5];

    const float ix = (gx + 1.0f) * 13.5f;
    const float iy = (gy + 1.0f) * 13.5f;

    const float x0f = floorf(ix);
    const float y0f = floorf(iy);
    const float wx = ix - x0f;
    const float wy = iy - y0f;

    int x0 = (int)x0f; x0 = min(max(x0, 0), 27);
    int x1 = min(x0 + 1, 27);
    int y0 = (int)y0f; y0 = min(max(y0, 0), 27);
    int y1 = min(y0 + 1, 27);

    const float* img = x + (size_t)n * 784;
    const float v00 = img[y0 * 28 + x0];
    const float v01 = img[y0 * 28 + x1];
    const float v10 = img[y1 * 28 + x0];
    const float v11 = img[y1 * 28 + x1];

    const float top = v00 * (1.0f - wx) + v01 * wx;
    const float bot = v10 * (1.0f - wx) + v11 * wx;
    out[idx] = top * (1.0f - wy) + bot * wy;
}

// ---------------- launcher ----------------
extern "C" void kernel_launch(void* const* d_in, const int* in_sizes, int n_in,
                              void* d_out, int out_size) {
    const float* x  = (const float*)d_in[0];
    const float* w1 = (const float*)d_in[1];
    const float* g1 = (const float*)d_in[2];
    const float* b1 = (const float*)d_in[3];
    const float* w2 = (const float*)d_in[4];
    const float* g2 = (const float*)d_in[5];
    const float* b2 = (const float*)d_in[6];
    const float* w3 = (const float*)d_in[7];
    const float* g3 = (const float*)d_in[8];
    const float* b3 = (const float*)d_in[9];
    const float* fw = (const float*)d_in[10];
    const float* fb = (const float*)d_in[11];
    float* out = (float*)d_out;

    k0_zero<<<1, 512>>>();
    k1_conv1<<<NN / 2, 176>>>(x, w1);
    k3_conv2<<<NN / 8, 128>>>(w2, g1, b1);
    k5_conv3stats<<<NN / 8, 128>>>(w3, g2, b2);
    k6_theta<<<NN, 128>>>(w3, g2, b2, g3, b3, fw, fb);
    k7_sample<<<(NN * 784 + 255) / 256, 256>>>(x, out);
}